// round 15
// baseline (speedup 1.0000x reference)
#include <cuda_runtime.h>
#include <cuda_fp16.h>
#include <cstdint>
#include <cstddef>
#include <math.h>

#define TT 2048
#define BB 2
#define EE 1024
#define HH 16
#define DD 64
#define NHEAD (BB*HH)   // 32
#define MM (TT*BB)      // 4096
#define NB 33           // relative-position bins
#define SRT 68          // rtab stride (floats)
#define SQR 36          // qrs/pws stride (elements)

// attn smem layout (bytes): 3 stages x (K 8192 | V 8192) swizzled 128B rows
#define STAGE_BYTES 16384
#define RT_OFF  49152
#define QRS_OFF 58128
#define PWS_OFF 62736
#define ATTN_SMEM_BYTES 71952

// Scratch (allocation-free rule: __device__ globals)
__device__ __half g_Xh[MM*EE];            // query in fp16
__device__ __half g_Wh[4*EE*EE];          // Wq,Wk,Wv,Wo in fp16
__device__ float  g_biasQKV[3*EE];        // bq|bk|bv
__device__ __half g_QKV[3*NHEAD*TT*DD];   // Q|K|V head-layout fp16
__device__ __half g_CTXh[MM*EE];

// ---------------------------------------------------------------------------
// helpers
// ---------------------------------------------------------------------------
__device__ __forceinline__ uint32_t h2pack(float x, float y) {
  __half2 t = __floats2half2_rn(x, y);
  return *reinterpret_cast<uint32_t*>(&t);
}
__device__ __forceinline__ float ex2f(float x) {
  float y;
  asm("ex2.approx.ftz.f32 %0, %1;" : "=f"(y) : "f"(x));
  return y;
}
__device__ __forceinline__ void mma16(float c[4], const uint32_t a[4], const uint32_t b[2]) {
  asm volatile(
    "mma.sync.aligned.m16n8k16.row.col.f32.f16.f16.f32 "
    "{%0,%1,%2,%3}, {%4,%5,%6,%7}, {%8,%9}, {%0,%1,%2,%3};\n"
    : "+f"(c[0]), "+f"(c[1]), "+f"(c[2]), "+f"(c[3])
    : "r"(a[0]), "r"(a[1]), "r"(a[2]), "r"(a[3]), "r"(b[0]), "r"(b[1]));
}
__device__ __forceinline__ uint32_t smem_u32(const void* p) {
  uint32_t a;
  asm("{ .reg .u64 t; cvta.to.shared.u64 t, %1; cvt.u32.u64 %0, t; }" : "=r"(a) : "l"(p));
  return a;
}
#define CPA16(d, s) asm volatile("cp.async.cg.shared.global [%0], [%1], 16;" :: "r"(d), "l"(s) : "memory")
#define CPA_COMMIT() asm volatile("cp.async.commit_group;" ::: "memory")
#define CPA_WAIT(n)  asm volatile("cp.async.wait_group %0;" :: "n"(n) : "memory")
#define LDMX4(r, a) \
  asm volatile("ldmatrix.sync.aligned.m8n8.x4.shared.b16 {%0,%1,%2,%3}, [%4];" \
    : "=r"((r)[0]), "=r"((r)[1]), "=r"((r)[2]), "=r"((r)[3]) : "r"(a))
#define LDMX4T(r, a) \
  asm volatile("ldmatrix.sync.aligned.m8n8.x4.trans.shared.b16 {%0,%1,%2,%3}, [%4];" \
    : "=r"((r)[0]), "=r"((r)[1]), "=r"((r)[2]), "=r"((r)[3]) : "r"(a))

// ---------------------------------------------------------------------------
// Fused fp32->fp16 conversion + bias concat.
// ---------------------------------------------------------------------------
__global__ __launch_bounds__(256) void cvt_all(
    const float* __restrict__ qy, const float* __restrict__ wq,
    const float* __restrict__ wk, const float* __restrict__ wv,
    const float* __restrict__ wo, const float* __restrict__ bq,
    const float* __restrict__ bk, const float* __restrict__ bv)
{
  int t = blockIdx.y;
  if (t == 5) {
    int idx = blockIdx.x * 256 + threadIdx.x;
    if (idx < 3*EE)
      g_biasQKV[idx] = (idx < EE) ? bq[idx]
                     : (idx < 2*EE) ? bk[idx - EE] : bv[idx - 2*EE];
    return;
  }
  const float* s;
  __half* d;
  int nblk;
  if (t == 0) { s = qy; d = g_Xh; nblk = MM*EE/2048; }
  else {
    s = (t == 1) ? wq : (t == 2) ? wk : (t == 3) ? wv : wo;
    d = g_Wh + (size_t)(t - 1) * EE * EE;
    nblk = EE*EE/2048;
  }
  if (blockIdx.x >= nblk) return;
  size_t i = ((size_t)blockIdx.x * 256 + threadIdx.x) * 8;
  float4 a = *(const float4*)(s + i);
  float4 b = *(const float4*)(s + i + 4);
  uint4 u = make_uint4(h2pack(a.x, a.y), h2pack(a.z, a.w),
                       h2pack(b.x, b.y), h2pack(b.z, b.w));
  *(uint4*)(d + i) = u;
}

// ---------------------------------------------------------------------------
// fp16 GEMM, 3-stage cp.async pipeline, ONE __syncthreads per iteration,
// issue-before-compute. BM=128, BN=128, BK=32. 256 threads = 8 warps.
// mode 1 (QKV fused): Q cols get scale 0.125*log2e, head-layout __half out.
// mode 0: fp32 row-major out.
// ---------------------------------------------------------------------------
__global__ __launch_bounds__(256, 2) void gemm3s(
    const __half* __restrict__ Xh, const __half* __restrict__ Wh,
    const float* __restrict__ bias, void* __restrict__ out, int mode)
{
  extern __shared__ char gsm[];
  uint32_t base = smem_u32(gsm);
  int tid = threadIdx.x, lane = tid & 31, warp = tid >> 5;
  int g = lane >> 2, q = lane & 3;
  int warpM = warp & 1, warpN = warp >> 1;
  int M0 = blockIdx.y * 128, N0 = blockIdx.x * 128;
  float acc[4][4][4] = {};

  int cr = tid >> 2, cc = tid & 3;
  uint32_t abase0 = (uint32_t)((warpM*64 + ((lane>>3)&1)*8 + (lane&7))*80 + (lane>>4)*16);
  uint32_t bbase0 = (uint32_t)((warpN*32 + (lane&7))*80 + (lane>>3)*16);

  auto issue = [&](int k0, int st) {
    uint32_t dx = base + (uint32_t)st*20480u + cr*80 + cc*16;
    const char* sx = (const char*)(Xh + (size_t)(M0 + cr)*EE + k0) + cc*16;
    const char* sw = (const char*)(Wh + (size_t)(N0 + cr)*EE + k0) + cc*16;
    CPA16(dx, sx);                 CPA16(dx + 64*80, sx + (size_t)64*EE*2);
    CPA16(dx + 10240, sw);         CPA16(dx + 10240 + 64*80, sw + (size_t)64*EE*2);
  };
  issue(0, 0);  CPA_COMMIT();
  issue(32, 1); CPA_COMMIT();

  int st = 0;
  for (int i = 0; i < 32; i++) {
    CPA_WAIT(1);
    __syncthreads();
    if (i + 2 < 32) { int st2 = st + 2; if (st2 >= 3) st2 -= 3; issue((i + 2) * 32, st2); }
    CPA_COMMIT();
    uint32_t sbase = base + (uint32_t)st*20480u;
    uint32_t ab = sbase + abase0;
    uint32_t bb = sbase + 10240 + bbase0;
    uint32_t b[4][4];
#pragma unroll
    for (int nt = 0; nt < 4; nt++) LDMX4(b[nt], bb + nt*640);
#pragma unroll
    for (int kb = 0; kb < 2; kb++) {
      uint32_t a[4][4];
#pragma unroll
      for (int mt = 0; mt < 4; mt++) LDMX4(a[mt], ab + mt*1280 + kb*32);
#pragma unroll
      for (int mt = 0; mt < 4; mt++)
#pragma unroll
        for (int nt = 0; nt < 4; nt++)
          mma16(acc[mt][nt], a[mt], &b[nt][kb*2]);
    }
    st = (st == 2) ? 0 : st + 1;
  }

  int mat = N0 >> 10;
  float scale = (mode && mat == 0) ? 0.1803368801111f : 1.0f;  // 0.125*log2(e)
#pragma unroll
  for (int mt = 0; mt < 4; mt++) {
    int r0 = M0 + warpM*64 + mt*16 + g;
#pragma unroll
    for (int nt = 0; nt < 4; nt++) {
      int col = N0 + warpN*32 + nt*8 + 2*q;
      float2 bv = *(const float2*)&bias[col];
      float o00 = (acc[mt][nt][0] + bv.x) * scale;
      float o01 = (acc[mt][nt][1] + bv.y) * scale;
      float o10 = (acc[mt][nt][2] + bv.x) * scale;
      float o11 = (acc[mt][nt][3] + bv.y) * scale;
      if (mode) {
        __half* oh = (__half*)out + (size_t)mat * NHEAD * TT * DD;
        int cm = col & 1023;
        int h = cm >> 6, d = cm & 63;
        int t0 = r0 >> 1, b0 = r0 & 1, n0h = b0*HH + h;
        *(__half2*)&oh[((size_t)(n0h*TT + t0))*DD + d] = __floats2half2_rn(o00, o01);
        int r1 = r0 + 8;
        int t1 = r1 >> 1, b1 = r1 & 1, n1h = b1*HH + h;
        *(__half2*)&oh[((size_t)(n1h*TT + t1))*DD + d] = __floats2half2_rn(o10, o11);
      } else {
        float* of = (float*)out;
        *(float2*)&of[(size_t)r0*EE + col]     = make_float2(o00, o01);
        *(float2*)&of[(size_t)(r0+8)*EE + col] = make_float2(o10, o11);
      }
    }
  }
}

// ---------------------------------------------------------------------------
// Flash attention, no online max, fp16 mma, 3-stage cp.async, one barrier per
// tile. S-phase PIPELINED: per key-block pair, MMA -> bias+ex2+pack -> aP ->
// ones-MMA, overlapping MUFU with the next pair's tensor work.
// 128 threads = 4 warps; warp w owns rows [w*16, w*16+16).
// ---------------------------------------------------------------------------
__global__ __launch_bounds__(128, 3) void attn_kernel(
    const float* __restrict__ rk_table, const float* __restrict__ rv_table)
{
  extern __shared__ char sm_[];
  float*  rtab = (float*)(sm_ + RT_OFF);
  __half* qrs  = (__half*)(sm_ + QRS_OFF);
  float*  pws  = (float*)(sm_ + PWS_OFF);
  uint32_t sb = smem_u32(sm_);

  int n  = blockIdx.y;
  int R0 = blockIdx.x * 64;
  int tid = threadIdx.x;
  int lane = tid & 31, warp = tid >> 5;
  int g = lane >> 2, q = lane & 3;
  int W0 = warp * 16;
  int r0l = W0 + g, r1l = r0l + 8;
  int l7 = lane & 7;

  const __half* Qg = g_QKV + (size_t)n * TT * DD;
  const __half* Kg = g_QKV + (size_t)(NHEAD + n) * TT * DD;
  const __half* Vg = g_QKV + (size_t)(2*NHEAD + n) * TT * DD;

  // ---- prologue: Q tile -> stage0 K region (swizzled) ----
#pragma unroll
  for (int j = 0; j < 4; j++) {
    int idx = tid + j*128;
    int r = idx >> 3, c8 = idx & 7;
    uint32_t dst = sb + r*128 + (((c8 ^ (r & 7)) & 7) << 4);
    CPA16(dst, (const char*)(Qg + (size_t)(R0 + r)*DD) + c8*16);
  }
  CPA_COMMIT();
  for (int idx = tid; idx < NB*64; idx += 128)
    rtab[(idx >> 6)*SRT + (idx & 63)] = rk_table[idx];
  for (int idx = tid; idx < 64*SQR; idx += 128)
    pws[idx] = 0.f;
  CPA_WAIT(0);
  __syncthreads();

  // ---- hoist Q A-fragments via ldmatrix (swizzled addresses) ----
  uint32_t qa[4][4];
  {
    int row = W0 + ((lane>>3)&1)*8 + l7;
    uint32_t rowb = sb + row*128;
#pragma unroll
    for (int kb = 0; kb < 4; kb++) {
      int cc = (lane>>4) + kb*2;
      LDMX4(qa[kb], rowb + (((cc ^ l7) & 7) << 4));
    }
  }
  // ---- QR bias: qrs[r][j] = sum_d Q[r][d]*rk[j][d]  (fp16 store) ----
  {
    int r = tid >> 1;
    int rs7 = r & 7;
    for (int j = (tid & 1); j < NB; j += 2) {
      float s = 0.f;
#pragma unroll 8
      for (int d = 0; d < 64; d += 2) {
        int c = d >> 3;
        __half2 h = *(__half2*)(sm_ + r*128 + (((c ^ rs7) & 7) << 4) + (d & 7)*2);
        float2 f = __half22float2(h);
        s += f.x * rtab[j*SRT + d] + f.y * rtab[j*SRT + d + 1];
      }
      qrs[r*SQR + j] = __float2half(s);
    }
  }

  float accO[8][4] = {};
  float accS[4] = {};
  float b0r0 = 0.f, b32r0 = 0.f, b0r1 = 0.f, b32r1 = 0.f;
  __syncthreads();   // Q frags + qrs done; stage0 reusable; rtab(rk) dead

  // preload rv into rtab NOW (overlaps with mainloop; epilogue needs no load)
  for (int idx = tid; idx < NB*64; idx += 128)
    rtab[(idx >> 6)*SRT + (idx & 63)] = rv_table[idx];

  // hoisted per-row off-diagonal biases
  float bOut0r0 = __half2float(qrs[r0l*SQR + 0]);
  float bOut32r0 = __half2float(qrs[r0l*SQR + 32]);
  float bOut0r1 = __half2float(qrs[r1l*SQR + 0]);
  float bOut32r1 = __half2float(qrs[r1l*SQR + 32]);

  auto issue_tile = [&](int tIdx, int st) {
    uint32_t kb = sb + (uint32_t)st*STAGE_BYTES;
    uint32_t vb = kb + 8192;
#pragma unroll
    for (int j = 0; j < 4; j++) {
      int idx = tid + j*128;
      int r = idx >> 3, c8 = idx & 7;
      uint32_t off = r*128 + (((c8 ^ (r & 7)) & 7) << 4);
      CPA16(kb + off, (const char*)(Kg + (size_t)(tIdx*64 + r)*DD) + c8*16);
      CPA16(vb + off, (const char*)(Vg + (size_t)(tIdx*64 + r)*DD) + c8*16);
    }
  };
  issue_tile(0, 0); CPA_COMMIT();
  issue_tile(1, 1); CPA_COMMIT();

  uint32_t koff1 = (uint32_t)((((lane>>3) ^ l7) & 7) << 4);
  uint32_t koff2 = (uint32_t)(((((lane>>3)+4) ^ l7) & 7) << 4);
  uint32_t krow  = (uint32_t)(l7*128);
  const uint32_t bOnes[2] = { 0x3C003C00u, 0x3C003C00u };

  int st = 0;
  for (int i = 0; i < 32; i++) {
    int C0 = i * 64;
    CPA_WAIT(1);
    __syncthreads();
    if (i + 2 < 32) { int st2 = st + 2; if (st2 >= 3) st2 -= 3; issue_tile(i + 2, st2); }
    CPA_COMMIT();

    uint32_t kstage = sb + (uint32_t)st*STAGE_BYTES;
    uint32_t vstage = kstage + 8192;
    uint32_t kb1 = kstage + krow + koff1;
    uint32_t kb2 = kstage + krow + koff2;
    uint32_t vrow = vstage + (uint32_t)lane*128;

    int Delta = C0 - R0 - W0;
    bool diag = (Delta <= 31) && (Delta >= -79);
    float bias0 = 0.f, bias1 = 0.f;
    if (!diag) {
      bias0 = (Delta > 0) ? bOut32r0 : bOut0r0;
      bias1 = (Delta > 0) ? bOut32r1 : bOut0r1;
    }

    // ---- S-phase: per key-block pair: MMA -> exp -> pack -> ones-MMA ----
    float sprev0 = accS[0], sprev1 = accS[2];
    uint32_t aP[4][4];
#pragma unroll
    for (int t = 0; t < 4; t++) {
      float pa[4] = {0.f, 0.f, 0.f, 0.f}, pb[4] = {0.f, 0.f, 0.f, 0.f};
      {
        uint32_t bk[8];
        LDMX4(bk,     kb1 + (2*t)*1024);
        LDMX4(bk + 4, kb2 + (2*t)*1024);
        mma16(pa, qa[0], bk + 0);
        mma16(pa, qa[1], bk + 2);
        mma16(pa, qa[2], bk + 4);
        mma16(pa, qa[3], bk + 6);
      }
      {
        uint32_t bk[8];
        LDMX4(bk,     kb1 + (2*t+1)*1024);
        LDMX4(bk + 4, kb2 + (2*t+1)*1024);
        mma16(pb, qa[0], bk + 0);
        mma16(pb, qa[1], bk + 2);
        mma16(pb, qa[2], bk + 4);
        mma16(pb, qa[3], bk + 6);
      }
      if (!diag) {
        aP[t][0] = h2pack(ex2f(pa[0] + bias0), ex2f(pa[1] + bias0));
        aP[t][1] = h2pack(ex2f(pa[2] + bias1), ex2f(pa[3] + bias1));
        aP[t][2] = h2pack(ex2f(pb[0] + bias0), ex2f(pb[1] + bias0));
        aP[t][3] = h2pack(ex2f(pb[2] + bias1), ex2f(pb[3] + bias1));
      } else {
        int cb0 = C0 + t*16 + 2*q;          // pa col base; pb at +8
        int j0 = min(16, max(-16, cb0     - (R0 + r0l))) + 16;
        int j1 = min(16, max(-16, cb0 + 1 - (R0 + r0l))) + 16;
        int j2 = min(16, max(-16, cb0     - (R0 + r1l))) + 16;
        int j3 = min(16, max(-16, cb0 + 1 - (R0 + r1l))) + 16;
        float v0 = ex2f(pa[0] + __half2float(qrs[r0l*SQR + j0]));
        float v1 = ex2f(pa[1] + __half2float(qrs[r0l*SQR + j1]));
        float v2 = ex2f(pa[2] + __half2float(qrs[r1l*SQR + j2]));
        float v3 = ex2f(pa[3] + __half2float(qrs[r1l*SQR + j3]));
        atomicAdd(&pws[r0l*SQR + j0], v0);
        atomicAdd(&pws[r0l*SQR + j1], v1);
        atomicAdd(&pws[r1l*SQR + j2], v2);
        atomicAdd(&pws[r1l*SQR + j3], v3);
        aP[t][0] = h2pack(v0, v1);
        aP[t][1] = h2pack(v2, v3);
        int cb1 = cb0 + 8;
        int j4 = min(16, max(-16, cb1     - (R0 + r0l))) + 16;
        int j5 = min(16, max(-16, cb1 + 1 - (R0 + r0l))) + 16;
        int j6 = min(16, max(-16, cb1     - (R0 + r1l))) + 16;
        int j7 = min(16, max(-16, cb1 + 1 - (R0 + r1l))) + 16;
        float w0 = ex2f(pb[0] + __half2float(qrs[r0l*SQR + j4]));
        float w1 = ex2f(pb[1] + __half2float(qrs[r0l*SQR + j5]));
        float w2 = ex2f(pb[2] + __half2float(qrs[r1l*SQR + j6]));
        float w3 = ex2f(pb[3] + __half2float(qrs[r1l*SQR + j7]));
        atomicAdd(&pws[r0l*SQR + j4], w0);
        atomicAdd(&pws[r0l*SQR + j5], w1);
        atomicAdd(&pws[r1l*SQR + j6], w2);
        atomicAdd(&pws[r1l*SQR + j7], w3);
        aP[t][2] = h2pack(w0, w1);
        aP[t][3] = h2pack(w2, w3);
      }
      mma16(accS, aP[t], bOnes);
    }
    if (!diag) {
      float rs0 = accS[0] - sprev0, rs1 = accS[2] - sprev1;
      if (Delta > 0) { b32r0 += rs0; b32r1 += rs1; }
      else           { b0r0  += rs0; b0r1  += rs1; }
    }

    // ---- O += P V ----
#pragma unroll
    for (int nt2 = 0; nt2 < 8; nt2++) {
      uint32_t voff = (uint32_t)(((nt2 ^ l7) & 7) << 4);
      uint32_t bv[8];
      LDMX4T(bv,     vrow + voff);
      LDMX4T(bv + 4, vrow + 4096 + voff);
      mma16(accO[nt2], aP[0], bv + 0);
      mma16(accO[nt2], aP[1], bv + 2);
      mma16(accO[nt2], aP[2], bv + 4);
      mma16(accO[nt2], aP[3], bv + 6);
    }

    st = (st == 2) ? 0 : st + 1;
  }

  // ---- epilogue: O += pw @ rv (rtab preloaded); l = accS; store ----
  __syncwarp();
#pragma unroll 4
  for (int j = 0; j < NB; j++) {
    float w0 = pws[r0l*SQR + j];
    float w1 = pws[r1l*SQR + j];
    if (j == 0)  { w0 += b0r0;  w1 += b0r1; }
    if (j == 32) { w0 += b32r0; w1 += b32r1; }
#pragma unroll
    for (int nt2 = 0; nt2 < 8; nt2++) {
      float2 rvv = *(const float2*)&rtab[j*SRT + nt2*8 + 2*q];
      accO[nt2][0] += w0*rvv.x; accO[nt2][1] += w0*rvv.y;
      accO[nt2][2] += w1*rvv.x; accO[nt2][3] += w1*rvv.y;
    }
  }
  float inv0 = 1.f / accS[0], inv1 = 1.f / accS[2];
  int b_ = n >> 4, h = n & 15;
  int gr0 = R0 + r0l, gr1 = R0 + r1l;
#pragma unroll
  for (int nt2 = 0; nt2 < 8; nt2++) {
    int col = h*DD + nt2*8 + 2*q;
    *(__half2*)&g_CTXh[((size_t)(gr0*BB + b_))*EE + col] =
        __floats2half2_rn(accO[nt2][0]*inv0, accO[nt2][1]*inv0);
    *(__half2*)&g_CTXh[((size_t)(gr1*BB + b_))*EE + col] =
        __floats2half2_rn(accO[nt2][2]*inv1, accO[nt2][3]*inv1);
  }
}

// ---------------------------------------------------------------------------
extern "C" void kernel_launch(void* const* d_in, const int* in_sizes, int n_in,
                              void* d_out, int out_size)
{
  const float* query = (const float*)d_in[0];
  const float* Wq    = (const float*)d_in[1];
  const float* bq    = (const float*)d_in[2];
  const float* Wk    = (const float*)d_in[3];
  const float* bk    = (const float*)d_in[4];
  const float* Wv    = (const float*)d_in[5];
  const float* bv    = (const float*)d_in[6];
  const float* Wo    = (const float*)d_in[7];
  const float* bo    = (const float*)d_in[8];
  const float* rk    = (const float*)d_in[9];
  const float* rv    = (const float*)d_in[10];
  float* out = (float*)d_out;

  void *pXh_, *pWh_, *pBias_, *pQKV_, *pCTX_;
  cudaGetSymbolAddress(&pXh_,  g_Xh);
  cudaGetSymbolAddress(&pWh_,  g_Wh);
  cudaGetSymbolAddress(&pBias_, g_biasQKV);
  cudaGetSymbolAddress(&pQKV_, g_QKV);
  cudaGetSymbolAddress(&pCTX_, g_CTXh);
  const __half* pXh  = (const __half*)pXh_;
  const __half* pWh  = (const __half*)pWh_;
  const float*  pBias = (const float*)pBias_;
  const __half* pCTX = (const __half*)pCTX_;

  const int GEMM_SMEM = 61440;   // 3 stages x 20480
  cudaFuncSetAttribute(gemm3s, cudaFuncAttributeMaxDynamicSharedMemorySize,
                       GEMM_SMEM);
  cudaFuncSetAttribute(attn_kernel, cudaFuncAttributeMaxDynamicSharedMemorySize,
                       ATTN_SMEM_BYTES);

  cvt_all<<<dim3(MM*EE/2048, 6), 256>>>(query, Wq, Wk, Wv, Wo, bq, bk, bv);
  gemm3s<<<dim3(3*EE/128, MM/128), 256, GEMM_SMEM>>>(pXh, pWh, pBias, pQKV_, 1);
  attn_kernel<<<dim3(TT/64, NHEAD), 128, ATTN_SMEM_BYTES>>>(rk, rv);
  gemm3s<<<dim3(EE/128, MM/128), 256, GEMM_SMEM>>>(
      pCTX, pWh + 3*(size_t)EE*EE, bo, out, 0);
}

// round 17
// speedup vs baseline: 1.0684x; 1.0684x over previous
#include <cuda_runtime.h>
#include <cuda_fp16.h>
#include <cstdint>
#include <cstddef>
#include <math.h>

#define TT 2048
#define BB 2
#define EE 1024
#define HH 16
#define DD 64
#define NHEAD (BB*HH)   // 32
#define MM (TT*BB)      // 4096
#define NB 33           // relative-position bins
#define SRT 68          // rtab stride (floats)
#define SQR 36          // qrs/pws stride (elements)

// attn smem layout (bytes): 3 stages x (K 8192 | V 8192) swizzled 128B rows
#define STAGE_BYTES 16384
#define RT_OFF  49152
#define QRS_OFF 58128
#define PWS_OFF 62736
#define ATTN_SMEM_BYTES 71952

// gemm smem: 3 stages x (X 16384 | W 16384) swizzled 128B rows
#define GST 32768
#define GEMM_SMEM_BYTES (3*GST)

// Scratch (allocation-free rule: __device__ globals)
__device__ __half g_Xh[MM*EE];            // query in fp16
__device__ __half g_Wh[4*EE*EE];          // Wq,Wk,Wv,Wo in fp16
__device__ float  g_biasQKV[3*EE];        // bq|bk|bv
__device__ __half g_QKV[3*NHEAD*TT*DD];   // Q|K|V head-layout fp16
__device__ __half g_CTXh[MM*EE];

// ---------------------------------------------------------------------------
// helpers
// ---------------------------------------------------------------------------
__device__ __forceinline__ uint32_t h2pack(float x, float y) {
  __half2 t = __floats2half2_rn(x, y);
  return *reinterpret_cast<uint32_t*>(&t);
}
__device__ __forceinline__ float ex2f(float x) {
  float y;
  asm("ex2.approx.ftz.f32 %0, %1;" : "=f"(y) : "f"(x));
  return y;
}
__device__ __forceinline__ void mma16(float c[4], const uint32_t a[4], const uint32_t b[2]) {
  asm volatile(
    "mma.sync.aligned.m16n8k16.row.col.f32.f16.f16.f32 "
    "{%0,%1,%2,%3}, {%4,%5,%6,%7}, {%8,%9}, {%0,%1,%2,%3};\n"
    : "+f"(c[0]), "+f"(c[1]), "+f"(c[2]), "+f"(c[3])
    : "r"(a[0]), "r"(a[1]), "r"(a[2]), "r"(a[3]), "r"(b[0]), "r"(b[1]));
}
__device__ __forceinline__ uint32_t smem_u32(const void* p) {
  uint32_t a;
  asm("{ .reg .u64 t; cvta.to.shared.u64 t, %1; cvt.u32.u64 %0, t; }" : "=r"(a) : "l"(p));
  return a;
}
#define CPA16(d, s) asm volatile("cp.async.cg.shared.global [%0], [%1], 16;" :: "r"(d), "l"(s) : "memory")
#define CPA_COMMIT() asm volatile("cp.async.commit_group;" ::: "memory")
#define CPA_WAIT(n)  asm volatile("cp.async.wait_group %0;" :: "n"(n) : "memory")
#define LDMX4(r, a) \
  asm volatile("ldmatrix.sync.aligned.m8n8.x4.shared.b16 {%0,%1,%2,%3}, [%4];" \
    : "=r"((r)[0]), "=r"((r)[1]), "=r"((r)[2]), "=r"((r)[3]) : "r"(a))
#define LDMX4T(r, a) \
  asm volatile("ldmatrix.sync.aligned.m8n8.x4.trans.shared.b16 {%0,%1,%2,%3}, [%4];" \
    : "=r"((r)[0]), "=r"((r)[1]), "=r"((r)[2]), "=r"((r)[3]) : "r"(a))

// ---------------------------------------------------------------------------
// Fused fp32->fp16 conversion + bias concat.
// ---------------------------------------------------------------------------
__global__ __launch_bounds__(256) void cvt_all(
    const float* __restrict__ qy, const float* __restrict__ wq,
    const float* __restrict__ wk, const float* __restrict__ wv,
    const float* __restrict__ wo, const float* __restrict__ bq,
    const float* __restrict__ bk, const float* __restrict__ bv)
{
  int t = blockIdx.y;
  if (t == 5) {
    int idx = blockIdx.x * 256 + threadIdx.x;
    if (idx < 3*EE)
      g_biasQKV[idx] = (idx < EE) ? bq[idx]
                     : (idx < 2*EE) ? bk[idx - EE] : bv[idx - 2*EE];
    return;
  }
  const float* s;
  __half* d;
  int nblk;
  if (t == 0) { s = qy; d = g_Xh; nblk = MM*EE/2048; }
  else {
    s = (t == 1) ? wq : (t == 2) ? wk : (t == 3) ? wv : wo;
    d = g_Wh + (size_t)(t - 1) * EE * EE;
    nblk = EE*EE/2048;
  }
  if (blockIdx.x >= nblk) return;
  size_t i = ((size_t)blockIdx.x * 256 + threadIdx.x) * 8;
  float4 a = *(const float4*)(s + i);
  float4 b = *(const float4*)(s + i + 4);
  uint4 u = make_uint4(h2pack(a.x, a.y), h2pack(a.z, a.w),
                       h2pack(b.x, b.y), h2pack(b.z, b.w));
  *(uint4*)(d + i) = u;
}

// ---------------------------------------------------------------------------
// fp16 GEMM, BK=64, 3-stage cp.async, XOR-swizzled 128B rows, one barrier
// per iteration (16 iterations). BM=128, BN=128. 256 threads = 8 warps
// (2M x 4N), warp tile 64x32.
// mode 1 (QKV fused): Q cols get scale 0.125*log2e, head-layout __half out.
// mode 0: fp32 row-major out.
// ---------------------------------------------------------------------------
__global__ __launch_bounds__(256, 2) void gemm64(
    const __half* __restrict__ Xh, const __half* __restrict__ Wh,
    const float* __restrict__ bias, void* __restrict__ out, int mode)
{
  extern __shared__ char gsm[];
  uint32_t base = smem_u32(gsm);
  int tid = threadIdx.x, lane = tid & 31, warp = tid >> 5;
  int g = lane >> 2, q = lane & 3;
  int l7 = lane & 7;
  int warpM = warp & 1, warpN = warp >> 1;
  int M0 = blockIdx.y * 128, N0 = blockIdx.x * 128;
  float acc[4][4][4] = {};

  // cp.async mapping: 1024 chunks per operand tile (128 rows x 8), 4/thread
  auto issue = [&](int k0, int st) {
    uint32_t sbase = base + (uint32_t)st * (uint32_t)GST;
#pragma unroll
    for (int j = 0; j < 4; j++) {
      int idx = tid + j*256;
      int r = idx >> 3, c8 = idx & 7;
      uint32_t off = r*128 + (((c8 ^ (r & 7)) & 7) << 4);
      CPA16(sbase + off,         (const char*)(Xh + (size_t)(M0 + r)*EE + k0) + c8*16);
      CPA16(sbase + 16384 + off, (const char*)(Wh + (size_t)(N0 + r)*EE + k0) + c8*16);
    }
  };
  issue(0, 0);  CPA_COMMIT();
  issue(64, 1); CPA_COMMIT();

  // fragment address bases (row&7 == l7 for all frag rows -> swizzle hoists)
  uint32_t arow = (uint32_t)(warpM*64 + ((lane>>3)&1)*8 + l7) * 128;
  uint32_t brow = (uint32_t)(warpN*32 + l7) * 128;
  uint32_t bcc0 = (uint32_t)((((lane>>3)    ) ^ l7) & 7) << 4;   // half 0
  uint32_t bcc1 = (uint32_t)((((lane>>3) + 4) ^ l7) & 7) << 4;   // half 1
  uint32_t acc0 = (uint32_t)((((lane>>4) + 0) ^ l7) & 7) << 4;   // kb0
  uint32_t acc1 = (uint32_t)((((lane>>4) + 2) ^ l7) & 7) << 4;   // kb1
  uint32_t acc2 = (uint32_t)((((lane>>4) + 4) ^ l7) & 7) << 4;   // kb2
  uint32_t acc3 = (uint32_t)((((lane>>4) + 6) ^ l7) & 7) << 4;   // kb3
  uint32_t accs[4] = { acc0, acc1, acc2, acc3 };

  int st = 0;
  for (int i = 0; i < 16; i++) {
    CPA_WAIT(1);
    __syncthreads();
    if (i + 2 < 16) { int st2 = st + 2; if (st2 >= 3) st2 -= 3; issue((i + 2) * 64, st2); }
    CPA_COMMIT();
    uint32_t xb = base + (uint32_t)st * (uint32_t)GST;
    uint32_t wb = xb + 16384;
#pragma unroll
    for (int half = 0; half < 2; half++) {
      uint32_t bcc = half ? bcc1 : bcc0;
      uint32_t b[4][4];
#pragma unroll
      for (int nt = 0; nt < 4; nt++) LDMX4(b[nt], wb + brow + nt*1024 + bcc);
#pragma unroll
      for (int kb2 = 0; kb2 < 2; kb2++) {
        uint32_t acol = accs[half*2 + kb2];
        uint32_t a[4][4];
#pragma unroll
        for (int mt = 0; mt < 4; mt++) LDMX4(a[mt], xb + arow + mt*2048 + acol);
#pragma unroll
        for (int mt = 0; mt < 4; mt++)
#pragma unroll
          for (int nt = 0; nt < 4; nt++)
            mma16(acc[mt][nt], a[mt], &b[nt][kb2*2]);
      }
    }
    st = (st == 2) ? 0 : st + 1;
  }

  int mat = N0 >> 10;
  float scale = (mode && mat == 0) ? 0.1803368801111f : 1.0f;  // 0.125*log2(e)
#pragma unroll
  for (int mt = 0; mt < 4; mt++) {
    int r0 = M0 + warpM*64 + mt*16 + g;
#pragma unroll
    for (int nt = 0; nt < 4; nt++) {
      int col = N0 + warpN*32 + nt*8 + 2*q;
      float2 bv = *(const float2*)&bias[col];
      float o00 = (acc[mt][nt][0] + bv.x) * scale;
      float o01 = (acc[mt][nt][1] + bv.y) * scale;
      float o10 = (acc[mt][nt][2] + bv.x) * scale;
      float o11 = (acc[mt][nt][3] + bv.y) * scale;
      if (mode) {
        __half* oh = (__half*)out + (size_t)mat * NHEAD * TT * DD;
        int cm = col & 1023;
        int h = cm >> 6, d = cm & 63;
        int t0 = r0 >> 1, b0 = r0 & 1, n0h = b0*HH + h;
        *(__half2*)&oh[((size_t)(n0h*TT + t0))*DD + d] = __floats2half2_rn(o00, o01);
        int r1 = r0 + 8;
        int t1 = r1 >> 1, b1 = r1 & 1, n1h = b1*HH + h;
        *(__half2*)&oh[((size_t)(n1h*TT + t1))*DD + d] = __floats2half2_rn(o10, o11);
      } else {
        float* of = (float*)out;
        *(float2*)&of[(size_t)r0*EE + col]     = make_float2(o00, o01);
        *(float2*)&of[(size_t)(r0+8)*EE + col] = make_float2(o10, o11);
      }
    }
  }
}

// ---------------------------------------------------------------------------
// Flash attention (round-14, proven): no online max, fp16 mma, 3-stage
// cp.async with ONE __syncthreads per tile, XOR-swizzled tiles, MMA row sums.
// 128 threads = 4 warps; warp w owns rows [w*16, w*16+16).
// ---------------------------------------------------------------------------
__global__ __launch_bounds__(128, 3) void attn_kernel(
    const float* __restrict__ rk_table, const float* __restrict__ rv_table)
{
  extern __shared__ char sm_[];
  float*  rtab = (float*)(sm_ + RT_OFF);
  __half* qrs  = (__half*)(sm_ + QRS_OFF);
  float*  pws  = (float*)(sm_ + PWS_OFF);
  uint32_t sb = smem_u32(sm_);

  int n  = blockIdx.y;
  int R0 = blockIdx.x * 64;
  int tid = threadIdx.x;
  int lane = tid & 31, warp = tid >> 5;
  int g = lane >> 2, q = lane & 3;
  int W0 = warp * 16;
  int r0l = W0 + g, r1l = r0l + 8;
  int l7 = lane & 7;

  const __half* Qg = g_QKV + (size_t)n * TT * DD;
  const __half* Kg = g_QKV + (size_t)(NHEAD + n) * TT * DD;
  const __half* Vg = g_QKV + (size_t)(2*NHEAD + n) * TT * DD;

  // ---- prologue: Q tile -> stage0 K region (swizzled) ----
#pragma unroll
  for (int j = 0; j < 4; j++) {
    int idx = tid + j*128;
    int r = idx >> 3, c8 = idx & 7;
    uint32_t dst = sb + r*128 + (((c8 ^ (r & 7)) & 7) << 4);
    CPA16(dst, (const char*)(Qg + (size_t)(R0 + r)*DD) + c8*16);
  }
  CPA_COMMIT();
  for (int idx = tid; idx < NB*64; idx += 128)
    rtab[(idx >> 6)*SRT + (idx & 63)] = rk_table[idx];
  for (int idx = tid; idx < 64*SQR; idx += 128)
    pws[idx] = 0.f;
  CPA_WAIT(0);
  __syncthreads();

  // ---- hoist Q A-fragments via ldmatrix (swizzled addresses) ----
  uint32_t qa[4][4];
  {
    int row = W0 + ((lane>>3)&1)*8 + l7;
    uint32_t rowb = sb + row*128;
#pragma unroll
    for (int kb = 0; kb < 4; kb++) {
      int cc = (lane>>4) + kb*2;
      LDMX4(qa[kb], rowb + (((cc ^ l7) & 7) << 4));
    }
  }
  // ---- QR bias: qrs[r][j] = sum_d Q[r][d]*rk[j][d]  (fp16 store) ----
  {
    int r = tid >> 1;
    int rs7 = r & 7;
    for (int j = (tid & 1); j < NB; j += 2) {
      float s = 0.f;
#pragma unroll 8
      for (int d = 0; d < 64; d += 2) {
        int c = d >> 3;
        __half2 h = *(__half2*)(sm_ + r*128 + (((c ^ rs7) & 7) << 4) + (d & 7)*2);
        float2 f = __half22float2(h);
        s += f.x * rtab[j*SRT + d] + f.y * rtab[j*SRT + d + 1];
      }
      qrs[r*SQR + j] = __float2half(s);
    }
  }

  float accO[8][4] = {};
  float accS[4] = {};
  float b0r0 = 0.f, b32r0 = 0.f, b0r1 = 0.f, b32r1 = 0.f;
  __syncthreads();   // Q frags + qrs done; stage0 reusable; rtab(rk) dead

  // preload rv into rtab NOW (overlaps with mainloop; epilogue needs no load)
  for (int idx = tid; idx < NB*64; idx += 128)
    rtab[(idx >> 6)*SRT + (idx & 63)] = rv_table[idx];

  // hoisted per-row off-diagonal biases
  float bOut0r0 = __half2float(qrs[r0l*SQR + 0]);
  float bOut32r0 = __half2float(qrs[r0l*SQR + 32]);
  float bOut0r1 = __half2float(qrs[r1l*SQR + 0]);
  float bOut32r1 = __half2float(qrs[r1l*SQR + 32]);

  auto issue_tile = [&](int tIdx, int st) {
    uint32_t kb = sb + (uint32_t)st*STAGE_BYTES;
    uint32_t vb = kb + 8192;
#pragma unroll
    for (int j = 0; j < 4; j++) {
      int idx = tid + j*128;
      int r = idx >> 3, c8 = idx & 7;
      uint32_t off = r*128 + (((c8 ^ (r & 7)) & 7) << 4);
      CPA16(kb + off, (const char*)(Kg + (size_t)(tIdx*64 + r)*DD) + c8*16);
      CPA16(vb + off, (const char*)(Vg + (size_t)(tIdx*64 + r)*DD) + c8*16);
    }
  };
  issue_tile(0, 0); CPA_COMMIT();
  issue_tile(1, 1); CPA_COMMIT();

  uint32_t koff1 = (uint32_t)((((lane>>3) ^ l7) & 7) << 4);
  uint32_t koff2 = (uint32_t)(((((lane>>3)+4) ^ l7) & 7) << 4);
  uint32_t krow  = (uint32_t)(l7*128);

  int st = 0;
  for (int i = 0; i < 32; i++) {
    int C0 = i * 64;
    CPA_WAIT(1);
    __syncthreads();
    if (i + 2 < 32) { int st2 = st + 2; if (st2 >= 3) st2 -= 3; issue_tile(i + 2, st2); }
    CPA_COMMIT();

    uint32_t kstage = sb + (uint32_t)st*STAGE_BYTES;
    uint32_t vstage = kstage + 8192;
    uint32_t kb1 = kstage + krow + koff1;
    uint32_t kb2 = kstage + krow + koff2;
    uint32_t vrow = vstage + (uint32_t)lane*128;

    // ---- S = Q K^T ----
    float p[8][4] = {};
#pragma unroll
    for (int nt = 0; nt < 8; nt++) {
      uint32_t bk[8];
      LDMX4(bk,     kb1 + nt*1024);
      LDMX4(bk + 4, kb2 + nt*1024);
      mma16(p[nt], qa[0], bk + 0);
      mma16(p[nt], qa[1], bk + 2);
      mma16(p[nt], qa[2], bk + 4);
      mma16(p[nt], qa[3], bk + 6);
    }

    // ---- bias + exp2 (no max subtraction: scores bounded) ----
    int Delta = C0 - R0 - W0;
    bool diag = (Delta <= 31) && (Delta >= -79);
    if (!diag) {
      float bias0 = (Delta > 0) ? bOut32r0 : bOut0r0;
      float bias1 = (Delta > 0) ? bOut32r1 : bOut0r1;
#pragma unroll
      for (int nt = 0; nt < 8; nt++) {
        p[nt][0] = ex2f(p[nt][0] + bias0);
        p[nt][1] = ex2f(p[nt][1] + bias0);
        p[nt][2] = ex2f(p[nt][2] + bias1);
        p[nt][3] = ex2f(p[nt][3] + bias1);
      }
    } else {
      // merged: bias + exp + histogram scatter (jb computed once)
#pragma unroll
      for (int nt = 0; nt < 8; nt++) {
#pragma unroll
        for (int i2 = 0; i2 < 4; i2++) {
          int row = (i2 >= 2) ? r1l : r0l;
          int rel = (C0 + nt*8 + 2*q + (i2 & 1)) - (R0 + row);
          int jb = min(16, max(-16, rel)) + 16;
          float v = ex2f(p[nt][i2] + __half2float(qrs[row*SQR + jb]));
          p[nt][i2] = v;
          atomicAdd(&pws[row*SQR + jb], v);
        }
      }
    }

    // ---- O += P V ; accS += P·1 (cumulative row sum = l) ----
    float sprev0 = accS[0], sprev1 = accS[2];
    uint32_t aP[4][4];
#pragma unroll
    for (int kb = 0; kb < 4; kb++) {
      aP[kb][0] = h2pack(p[2*kb][0],   p[2*kb][1]);
      aP[kb][1] = h2pack(p[2*kb][2],   p[2*kb][3]);
      aP[kb][2] = h2pack(p[2*kb+1][0], p[2*kb+1][1]);
      aP[kb][3] = h2pack(p[2*kb+1][2], p[2*kb+1][3]);
    }
#pragma unroll
    for (int nt2 = 0; nt2 < 8; nt2++) {
      uint32_t voff = (uint32_t)(((nt2 ^ l7) & 7) << 4);
      uint32_t bv[8];
      LDMX4T(bv,     vrow + voff);
      LDMX4T(bv + 4, vrow + 4096 + voff);
      mma16(accO[nt2], aP[0], bv + 0);
      mma16(accO[nt2], aP[1], bv + 2);
      mma16(accO[nt2], aP[2], bv + 4);
      mma16(accO[nt2], aP[3], bv + 6);
    }
    {
      uint32_t bOnes[2] = { 0x3C003C00u, 0x3C003C00u };
      mma16(accS, aP[0], bOnes);
      mma16(accS, aP[1], bOnes);
      mma16(accS, aP[2], bOnes);
      mma16(accS, aP[3], bOnes);
    }
    if (!diag) {
      float rs0 = accS[0] - sprev0, rs1 = accS[2] - sprev1;
      if (Delta > 0) { b32r0 += rs0; b32r1 += rs1; }
      else           { b0r0  += rs0; b0r1  += rs1; }
    }

    st = (st == 2) ? 0 : st + 1;
  }

  // ---- epilogue: O += pw @ rv (rtab preloaded); l = accS; store ----
  __syncwarp();
#pragma unroll 4
  for (int j = 0; j < NB; j++) {
    float w0 = pws[r0l*SQR + j];
    float w1 = pws[r1l*SQR + j];
    if (j == 0)  { w0 += b0r0;  w1 += b0r1; }
    if (j == 32) { w0 += b32r0; w1 += b32r1; }
#pragma unroll
    for (int nt2 = 0; nt2 < 8; nt2++) {
      float2 rvv = *(const float2*)&rtab[j*SRT + nt2*8 + 2*q];
      accO[nt2][0] += w0*rvv.x; accO[nt2][1] += w0*rvv.y;
      accO[nt2][2] += w1*rvv.x; accO[nt2][3] += w1*rvv.y;
    }
  }
  float inv0 = 1.f / accS[0], inv1 = 1.f / accS[2];
  int b_ = n >> 4, h = n & 15;
  int gr0 = R0 + r0l, gr1 = R0 + r1l;
#pragma unroll
  for (int nt2 = 0; nt2 < 8; nt2++) {
    int col = h*DD + nt2*8 + 2*q;
    *(__half2*)&g_CTXh[((size_t)(gr0*BB + b_))*EE + col] =
        __floats2half2_rn(accO[nt2][0]*inv0, accO[nt2][1]*inv0);
    *(__half2*)&g_CTXh[((size_t)(gr1*BB + b_))*EE + col] =
        __floats2half2_rn(accO[nt2][2]*inv1, accO[nt2][3]*inv1);
  }
}

// ---------------------------------------------------------------------------
extern "C" void kernel_launch(void* const* d_in, const int* in_sizes, int n_in,
                              void* d_out, int out_size)
{
  const float* query = (const float*)d_in[0];
  const float* Wq    = (const float*)d_in[1];
  const float* bq    = (const float*)d_in[2];
  const float* Wk    = (const float*)d_in[3];
  const float* bk    = (const float*)d_in[4];
  const float* Wv    = (const float*)d_in[5];
  const float* bv    = (const float*)d_in[6];
  const float* Wo    = (const float*)d_in[7];
  const float* bo    = (const float*)d_in[8];
  const float* rk    = (const float*)d_in[9];
  const float* rv    = (const float*)d_in[10];
  float* out = (float*)d_out;

  void *pXh_, *pWh_, *pBias_, *pQKV_, *pCTX_;
  cudaGetSymbolAddress(&pXh_,  g_Xh);
  cudaGetSymbolAddress(&pWh_,  g_Wh);
  cudaGetSymbolAddress(&pBias_, g_biasQKV);
  cudaGetSymbolAddress(&pQKV_, g_QKV);
  cudaGetSymbolAddress(&pCTX_, g_CTXh);
  const __half* pXh  = (const __half*)pXh_;
  const __half* pWh  = (const __half*)pWh_;
  const float*  pBias = (const float*)pBias_;
  const __half* pCTX = (const __half*)pCTX_;

  cudaFuncSetAttribute(gemm64, cudaFuncAttributeMaxDynamicSharedMemorySize,
                       GEMM_SMEM_BYTES);
  cudaFuncSetAttribute(attn_kernel, cudaFuncAttributeMaxDynamicSharedMemorySize,
                       ATTN_SMEM_BYTES);

  cvt_all<<<dim3(MM*EE/2048, 6), 256>>>(query, Wq, Wk, Wv, Wo, bq, bk, bv);
  gemm64<<<dim3(3*EE/128, MM/128), 256, GEMM_SMEM_BYTES>>>(pXh, pWh, pBias, pQKV_, 1);
  attn_kernel<<<dim3(TT/64, NHEAD), 128, ATTN_SMEM_BYTES>>>(rk, rv);
  gemm64<<<dim3(EE/128, MM/128), 256, GEMM_SMEM_BYTES>>>(
      pCTX, pWh + 3*(size_t)EE*EE, bo, out, 0);
}